// round 1
// baseline (speedup 1.0000x reference)
#include <cuda_runtime.h>
#include <math.h>

// Problem constants
#define TT    2048      // tokens (B*S)
#define DM    1024      // d_model
#define DFF   2048      // d_ff
#define NH    4096      // 2*d_ff
#define NE    16        // experts
#define NAg   4
#define NBg   4

// ---------------- device scratch (static, no allocations) ----------------
__device__ int   g_eidx[TT];
__device__ int   g_counts[NE];
__device__ int   g_offsets[NE + 1];
__device__ int   g_pos[NE];
__device__ int   g_perm[TT];
__device__ float g_probsum[NAg + NBg];
__device__ float g_ohsum[NAg + NBg];
__device__ float g_act[(size_t)TT * DFF];   // 16 MB activation scratch (sorted rows)

// ---------------- packed f32x2 helpers ----------------
__device__ __forceinline__ void fma2(unsigned long long &acc,
                                     unsigned long long a,
                                     unsigned long long b) {
    asm("fma.rn.f32x2 %0, %1, %2, %0;" : "+l"(acc) : "l"(a), "l"(b));
}
__device__ __forceinline__ unsigned long long pack2(float x, float y) {
    unsigned long long r;
    asm("mov.b64 %0, {%1, %2};" : "=l"(r) : "f"(x), "f"(y));
    return r;
}
__device__ __forceinline__ float2 unpack2(unsigned long long v) {
    float2 f;
    asm("mov.b64 {%0, %1}, %2;" : "=f"(f.x), "=f"(f.y) : "l"(v));
    return f;
}

// ---------------- kernel 0: zero accumulators ----------------
__global__ void zero_kernel() {
    int t = threadIdx.x;
    if (t < NE) g_counts[t] = 0;
    if (t < NAg + NBg) { g_probsum[t] = 0.f; g_ohsum[t] = 0.f; }
}

// ---------------- kernel 1: gating (one warp per token) ----------------
__global__ void gating_kernel(const float* __restrict__ x,
                              const float* __restrict__ Wga, const float* __restrict__ bga,
                              const float* __restrict__ Wgb, const float* __restrict__ bgb) {
    int warp = (blockIdx.x * blockDim.x + threadIdx.x) >> 5;
    int lane = threadIdx.x & 31;
    if (warp >= TT) return;
    const float* xr = x + (size_t)warp * DM;

    float acc[8];
#pragma unroll
    for (int j = 0; j < 8; j++) acc[j] = 0.f;

    for (int k = lane; k < DM; k += 32) {
        float xv = xr[k];
#pragma unroll
        for (int j = 0; j < 4; j++) acc[j]     += xv * Wga[k * 4 + j];
#pragma unroll
        for (int j = 0; j < 4; j++) acc[4 + j] += xv * Wgb[k * 4 + j];
    }
#pragma unroll
    for (int off = 16; off > 0; off >>= 1) {
#pragma unroll
        for (int j = 0; j < 8; j++)
            acc[j] += __shfl_xor_sync(0xFFFFFFFFu, acc[j], off);
    }
    if (lane == 0) {
        float la[4], lb[4];
#pragma unroll
        for (int j = 0; j < 4; j++) { la[j] = acc[j] + bga[j]; lb[j] = acc[4 + j] + bgb[j]; }

        // softmax + argmax (first max, like jnp.argmax)
        float ma = la[0]; int ia = 0;
#pragma unroll
        for (int j = 1; j < 4; j++) if (la[j] > ma) { ma = la[j]; ia = j; }
        float mb = lb[0]; int ib = 0;
#pragma unroll
        for (int j = 1; j < 4; j++) if (lb[j] > mb) { mb = lb[j]; ib = j; }

        float pa[4], pb[4], sa = 0.f, sb = 0.f;
#pragma unroll
        for (int j = 0; j < 4; j++) { pa[j] = expf(la[j] - ma); sa += pa[j]; }
#pragma unroll
        for (int j = 0; j < 4; j++) { pb[j] = expf(lb[j] - mb); sb += pb[j]; }
        float rsa = 1.f / sa, rsb = 1.f / sb;

        int e = ia * NBg + ib;
        g_eidx[warp] = e;
        atomicAdd(&g_counts[e], 1);
#pragma unroll
        for (int j = 0; j < 4; j++) {
            atomicAdd(&g_probsum[j],       pa[j] * rsa);
            atomicAdd(&g_probsum[4 + j],   pb[j] * rsb);
        }
        atomicAdd(&g_ohsum[ia], 1.f);
        atomicAdd(&g_ohsum[4 + ib], 1.f);
    }
}

// ---------------- kernel 2: scan + aux loss ----------------
__global__ void scan_kernel(float* __restrict__ out, int out_size) {
    if (threadIdx.x == 0) {
        int off = 0;
        for (int e = 0; e < NE; e++) {
            g_offsets[e] = off;
            g_pos[e] = off;
            off += g_counts[e];
        }
        g_offsets[NE] = off;

        if (out_size > TT * DM) {
            const float invT = 1.f / (float)TT;
            float auxA = 0.f, auxB = 0.f;
            for (int j = 0; j < 4; j++) auxA += (g_probsum[j]     * invT) * (g_ohsum[j]     * invT);
            for (int j = 0; j < 4; j++) auxB += (g_probsum[4 + j] * invT) * (g_ohsum[4 + j] * invT);
            out[TT * DM] = (float)NAg * auxA + (float)NBg * auxB;
        }
    }
}

// ---------------- kernel 3: scatter tokens into expert-sorted order ----------------
__global__ void scatter_kernel() {
    int t = blockIdx.x * blockDim.x + threadIdx.x;
    if (t >= TT) return;
    int e = g_eidx[t];
    int p = atomicAdd(&g_pos[e], 1);
    g_perm[p] = t;
}

// ---------------- kernel 4: GEMM1 + SwiGLU epilogue ----------------
// Per block: 128 token rows x (64 a-cols + 64 g-cols), K = 1024, BK = 16.
// Thread tile: 8 rows x (4 a-cols + 4 g-cols).
__global__ __launch_bounds__(256, 2)
void gemm1_kernel(const float* __restrict__ x,
                  const float* __restrict__ W1,
                  const float* __restrict__ b1) {
    const int e = blockIdx.z;
    const int off  = g_offsets[e];
    const int cnt  = g_offsets[e + 1] - off;
    const int row0 = blockIdx.y * 128;
    if (row0 >= cnt) return;
    const int n0 = blockIdx.x * 64;
    const int rowsv = min(128, cnt - row0);

    __shared__ float As[16][132];
    __shared__ float Bs[16][132];
    __shared__ int   toks[128];

    const int tid = threadIdx.x;
    const int tx = tid & 15, ty = tid >> 4;

    if (tid < 128) toks[tid] = (tid < rowsv) ? g_perm[off + row0 + tid] : -1;
    __syncthreads();

    const float* W1e = W1 + (size_t)e * DM * NH;

    unsigned long long acc_a[8][2], acc_g[8][2];
#pragma unroll
    for (int i = 0; i < 8; i++) {
        acc_a[i][0] = 0ull; acc_a[i][1] = 0ull;
        acc_g[i][0] = 0ull; acc_g[i][1] = 0ull;
    }

    const int lr = tid >> 1;             // A-load row
    const int lk = (tid & 1) * 8;        // A-load k offset

    for (int k0 = 0; k0 < DM; k0 += 16) {
        // ---- load A tile (gathered token rows) ----
        {
            int tok = toks[lr];
            float4 v0 = make_float4(0.f, 0.f, 0.f, 0.f);
            float4 v1 = v0;
            if (tok >= 0) {
                const float4* p = (const float4*)(x + (size_t)tok * DM + k0 + lk);
                v0 = p[0]; v1 = p[1];
            }
            As[lk + 0][lr] = v0.x; As[lk + 1][lr] = v0.y;
            As[lk + 2][lr] = v0.z; As[lk + 3][lr] = v0.w;
            As[lk + 4][lr] = v1.x; As[lk + 5][lr] = v1.y;
            As[lk + 6][lr] = v1.z; As[lk + 7][lr] = v1.w;
        }
        // ---- load B tile: cols [n0,n0+64) of a-half and g-half ----
#pragma unroll
        for (int p = 0; p < 2; p++) {
            int q  = tid + p * 256;
            int k  = q >> 5;
            int col = (q & 31) * 4;
            const float* src = (col < 64)
                ? (W1e + (size_t)(k0 + k) * NH + n0 + col)
                : (W1e + (size_t)(k0 + k) * NH + DFF + n0 + (col - 64));
            *(float4*)&Bs[k][col] = *(const float4*)src;
        }
        __syncthreads();

#pragma unroll
        for (int k = 0; k < 16; k++) {
            float4 a0 = *(const float4*)&As[k][ty * 8];
            float4 a1 = *(const float4*)&As[k][ty * 8 + 4];
            unsigned long long pa[8];
            pa[0] = pack2(a0.x, a0.x); pa[1] = pack2(a0.y, a0.y);
            pa[2] = pack2(a0.z, a0.z); pa[3] = pack2(a0.w, a0.w);
            pa[4] = pack2(a1.x, a1.x); pa[5] = pack2(a1.y, a1.y);
            pa[6] = pack2(a1.z, a1.z); pa[7] = pack2(a1.w, a1.w);

            float4 ba = *(const float4*)&Bs[k][tx * 4];
            float4 bg = *(const float4*)&Bs[k][64 + tx * 4];
            unsigned long long ba0 = pack2(ba.x, ba.y), ba1 = pack2(ba.z, ba.w);
            unsigned long long bg0 = pack2(bg.x, bg.y), bg1 = pack2(bg.z, bg.w);
#pragma unroll
            for (int i = 0; i < 8; i++) {
                fma2(acc_a[i][0], pa[i], ba0);
                fma2(acc_a[i][1], pa[i], ba1);
                fma2(acc_g[i][0], pa[i], bg0);
                fma2(acc_g[i][1], pa[i], bg1);
            }
        }
        __syncthreads();
    }

    // ---- epilogue: bias + a * silu(g) -> g_act (sorted rows) ----
    const float* b1e = b1 + (size_t)e * NH;
    const int ca = n0 + tx * 4;
    float bav[4], bgv[4];
#pragma unroll
    for (int c = 0; c < 4; c++) {
        bav[c] = b1e[ca + c];
        bgv[c] = b1e[DFF + ca + c];
    }
#pragma unroll
    for (int i = 0; i < 8; i++) {
        int r = ty * 8 + i;
        if (r < rowsv) {
            float2 a01 = unpack2(acc_a[i][0]), a23 = unpack2(acc_a[i][1]);
            float2 g01 = unpack2(acc_g[i][0]), g23 = unpack2(acc_g[i][1]);
            float av[4] = { a01.x, a01.y, a23.x, a23.y };
            float gv[4] = { g01.x, g01.y, g23.x, g23.y };
            float ov[4];
#pragma unroll
            for (int c = 0; c < 4; c++) {
                float aa = av[c] + bav[c];
                float gg = gv[c] + bgv[c];
                float s  = gg / (1.f + expf(-gg));   // silu(g)
                ov[c] = aa * s;
            }
            *(float4*)&g_act[(size_t)(off + row0 + r) * DFF + ca] =
                make_float4(ov[0], ov[1], ov[2], ov[3]);
        }
    }
}

// ---------------- kernel 5: GEMM2 + bias + scatter to output ----------------
// Per block: 128 rows x 128 cols, K = 2048, BK = 16. Thread tile 8x8.
__global__ __launch_bounds__(256, 2)
void gemm2_kernel(const float* __restrict__ W2,
                  const float* __restrict__ b2,
                  float* __restrict__ out) {
    const int e = blockIdx.z;
    const int off  = g_offsets[e];
    const int cnt  = g_offsets[e + 1] - off;
    const int row0 = blockIdx.y * 128;
    if (row0 >= cnt) return;
    const int n0 = blockIdx.x * 128;
    const int rowsv = min(128, cnt - row0);

    __shared__ float As[16][132];
    __shared__ float Bs[16][132];
    __shared__ int   toks[128];

    const int tid = threadIdx.x;
    const int tx = tid & 15, ty = tid >> 4;

    if (tid < 128) toks[tid] = (tid < rowsv) ? g_perm[off + row0 + tid] : -1;
    __syncthreads();

    const float* W2e = W2 + (size_t)e * DFF * DM;

    unsigned long long acc[8][4];
#pragma unroll
    for (int i = 0; i < 8; i++)
#pragma unroll
        for (int j = 0; j < 4; j++) acc[i][j] = 0ull;

    const int lr = tid >> 1;
    const int lk = (tid & 1) * 8;

    for (int k0 = 0; k0 < DFF; k0 += 16) {
        // ---- load A tile (sorted act rows: contiguous, no gather) ----
        {
            float4 v0 = make_float4(0.f, 0.f, 0.f, 0.f);
            float4 v1 = v0;
            if (lr < rowsv) {
                const float4* p =
                    (const float4*)(g_act + (size_t)(off + row0 + lr) * DFF + k0 + lk);
                v0 = p[0]; v1 = p[1];
            }
            As[lk + 0][lr] = v0.x; As[lk + 1][lr] = v0.y;
            As[lk + 2][lr] = v0.z; As[lk + 3][lr] = v0.w;
            As[lk + 4][lr] = v1.x; As[lk + 5][lr] = v1.y;
            As[lk + 6][lr] = v1.z; As[lk + 7][lr] = v1.w;
        }
        // ---- load B tile: W2[e][k0..k0+16, n0..n0+128) ----
#pragma unroll
        for (int p = 0; p < 2; p++) {
            int q  = tid + p * 256;
            int k  = q >> 5;
            int col = (q & 31) * 4;
            *(float4*)&Bs[k][col] =
                *(const float4*)(W2e + (size_t)(k0 + k) * DM + n0 + col);
        }
        __syncthreads();

#pragma unroll
        for (int k = 0; k < 16; k++) {
            float4 a0 = *(const float4*)&As[k][ty * 8];
            float4 a1 = *(const float4*)&As[k][ty * 8 + 4];
            unsigned long long pa[8];
            pa[0] = pack2(a0.x, a0.x); pa[1] = pack2(a0.y, a0.y);
            pa[2] = pack2(a0.z, a0.z); pa[3] = pack2(a0.w, a0.w);
            pa[4] = pack2(a1.x, a1.x); pa[5] = pack2(a1.y, a1.y);
            pa[6] = pack2(a1.z, a1.z); pa[7] = pack2(a1.w, a1.w);

            float4 b0 = *(const float4*)&Bs[k][tx * 8];
            float4 b1v = *(const float4*)&Bs[k][tx * 8 + 4];
            unsigned long long bb0 = pack2(b0.x,  b0.y),  bb1 = pack2(b0.z,  b0.w);
            unsigned long long bb2 = pack2(b1v.x, b1v.y), bb3 = pack2(b1v.z, b1v.w);
#pragma unroll
            for (int i = 0; i < 8; i++) {
                fma2(acc[i][0], pa[i], bb0);
                fma2(acc[i][1], pa[i], bb1);
                fma2(acc[i][2], pa[i], bb2);
                fma2(acc[i][3], pa[i], bb3);
            }
        }
        __syncthreads();
    }

    // ---- epilogue: bias + scatter rows back to token order ----
    const float* b2e = b2 + (size_t)e * DM;
    const int cb = n0 + tx * 8;
    float bv[8];
#pragma unroll
    for (int c = 0; c < 8; c++) bv[c] = b2e[cb + c];

#pragma unroll
    for (int i = 0; i < 8; i++) {
        int r = ty * 8 + i;
        if (r < rowsv) {
            int tok = toks[r];
            float2 y0 = unpack2(acc[i][0]), y1 = unpack2(acc[i][1]);
            float2 y2 = unpack2(acc[i][2]), y3 = unpack2(acc[i][3]);
            float* dst = out + (size_t)tok * DM + cb;
            *(float4*)(dst)     = make_float4(y0.x + bv[0], y0.y + bv[1],
                                              y1.x + bv[2], y1.y + bv[3]);
            *(float4*)(dst + 4) = make_float4(y2.x + bv[4], y2.y + bv[5],
                                              y3.x + bv[6], y3.y + bv[7]);
        }
    }
}

// ---------------- launch ----------------
extern "C" void kernel_launch(void* const* d_in, const int* in_sizes, int n_in,
                              void* d_out, int out_size) {
    const float* x   = (const float*)d_in[0];
    const float* W1  = (const float*)d_in[1];
    const float* b1  = (const float*)d_in[2];
    const float* W2  = (const float*)d_in[3];
    const float* b2  = (const float*)d_in[4];
    const float* Wga = (const float*)d_in[5];
    const float* bga = (const float*)d_in[6];
    const float* Wgb = (const float*)d_in[7];
    const float* bgb = (const float*)d_in[8];
    float* out = (float*)d_out;

    zero_kernel<<<1, 64>>>();
    gating_kernel<<<TT / 8, 256>>>(x, Wga, bga, Wgb, bgb);
    scan_kernel<<<1, 32>>>(out, out_size);
    scatter_kernel<<<TT / 256, 256>>>();
    gemm1_kernel<<<dim3(32, 16, NE), 256>>>(x, W1, b1);
    gemm2_kernel<<<dim3(8, 16, NE), 256>>>(W2, b2, out);
}

// round 2
// speedup vs baseline: 2.3847x; 2.3847x over previous
#include <cuda_runtime.h>
#include <math.h>
#include <stdint.h>

// Problem constants
#define TT    2048      // tokens (B*S)
#define DM    1024      // d_model
#define DFF   2048      // d_ff
#define NH    4096      // 2*d_ff
#define NE    16        // experts
#define NAg   4
#define NBg   4

// ---------------- device scratch (static, no allocations) ----------------
__device__ int   g_eidx[TT];
__device__ int   g_counts[NE];
__device__ int   g_offsets[NE + 1];
__device__ int   g_pos[NE];
__device__ int   g_perm[TT];
__device__ float g_probsum[NAg + NBg];
__device__ float g_ohsum[NAg + NBg];
__device__ float g_act[(size_t)TT * DFF];   // 16 MB activation scratch (sorted rows)

// ---------------- helpers ----------------
__device__ __forceinline__ uint32_t f2tf(float f) {
    uint32_t r;
    asm("cvt.rna.tf32.f32 %0, %1;" : "=r"(r) : "f"(f));
    return r;
}
__device__ __forceinline__ void mma_tf32(float c[4],
                                         const uint32_t a[4],
                                         const uint32_t b[2]) {
    asm volatile(
        "mma.sync.aligned.m16n8k8.row.col.f32.tf32.tf32.f32 "
        "{%0,%1,%2,%3}, {%4,%5,%6,%7}, {%8,%9}, {%0,%1,%2,%3};"
        : "+f"(c[0]), "+f"(c[1]), "+f"(c[2]), "+f"(c[3])
        : "r"(a[0]), "r"(a[1]), "r"(a[2]), "r"(a[3]), "r"(b[0]), "r"(b[1]));
}
__device__ __forceinline__ void cp16(uint32_t dst_smem, const void* src, int src_bytes) {
    asm volatile("cp.async.cg.shared.global [%0], [%1], 16, %2;"
                 :: "r"(dst_smem), "l"(src), "r"(src_bytes));
}
__device__ __forceinline__ void cp_commit() {
    asm volatile("cp.async.commit_group;");
}
__device__ __forceinline__ void cp_wait1() {
    asm volatile("cp.async.wait_group 1;");
}
__device__ __forceinline__ void cp_wait0() {
    asm volatile("cp.async.wait_group 0;");
}

// ---------------- kernel 0: zero accumulators ----------------
__global__ void zero_kernel() {
    int t = threadIdx.x;
    if (t < NE) g_counts[t] = 0;
    if (t < NAg + NBg) { g_probsum[t] = 0.f; g_ohsum[t] = 0.f; }
}

// ---------------- kernel 1: gating (one warp per token) ----------------
__global__ void gating_kernel(const float* __restrict__ x,
                              const float* __restrict__ Wga, const float* __restrict__ bga,
                              const float* __restrict__ Wgb, const float* __restrict__ bgb) {
    int warp = (blockIdx.x * blockDim.x + threadIdx.x) >> 5;
    int lane = threadIdx.x & 31;
    if (warp >= TT) return;
    const float* xr = x + (size_t)warp * DM;

    float acc[8];
#pragma unroll
    for (int j = 0; j < 8; j++) acc[j] = 0.f;

    for (int k = lane; k < DM; k += 32) {
        float xv = xr[k];
#pragma unroll
        for (int j = 0; j < 4; j++) acc[j]     += xv * Wga[k * 4 + j];
#pragma unroll
        for (int j = 0; j < 4; j++) acc[4 + j] += xv * Wgb[k * 4 + j];
    }
#pragma unroll
    for (int off = 16; off > 0; off >>= 1) {
#pragma unroll
        for (int j = 0; j < 8; j++)
            acc[j] += __shfl_xor_sync(0xFFFFFFFFu, acc[j], off);
    }
    if (lane == 0) {
        float la[4], lb[4];
#pragma unroll
        for (int j = 0; j < 4; j++) { la[j] = acc[j] + bga[j]; lb[j] = acc[4 + j] + bgb[j]; }

        float ma = la[0]; int ia = 0;
#pragma unroll
        for (int j = 1; j < 4; j++) if (la[j] > ma) { ma = la[j]; ia = j; }
        float mb = lb[0]; int ib = 0;
#pragma unroll
        for (int j = 1; j < 4; j++) if (lb[j] > mb) { mb = lb[j]; ib = j; }

        float pa[4], pb[4], sa = 0.f, sb = 0.f;
#pragma unroll
        for (int j = 0; j < 4; j++) { pa[j] = expf(la[j] - ma); sa += pa[j]; }
#pragma unroll
        for (int j = 0; j < 4; j++) { pb[j] = expf(lb[j] - mb); sb += pb[j]; }
        float rsa = 1.f / sa, rsb = 1.f / sb;

        int e = ia * NBg + ib;
        g_eidx[warp] = e;
        atomicAdd(&g_counts[e], 1);
#pragma unroll
        for (int j = 0; j < 4; j++) {
            atomicAdd(&g_probsum[j],       pa[j] * rsa);
            atomicAdd(&g_probsum[4 + j],   pb[j] * rsb);
        }
        atomicAdd(&g_ohsum[ia], 1.f);
        atomicAdd(&g_ohsum[4 + ib], 1.f);
    }
}

// ---------------- kernel 2: scan + aux loss ----------------
__global__ void scan_kernel(float* __restrict__ out, int out_size) {
    if (threadIdx.x == 0) {
        int off = 0;
        for (int e = 0; e < NE; e++) {
            g_offsets[e] = off;
            g_pos[e] = off;
            off += g_counts[e];
        }
        g_offsets[NE] = off;

        if (out_size > TT * DM) {
            const float invT = 1.f / (float)TT;
            float auxA = 0.f, auxB = 0.f;
            for (int j = 0; j < 4; j++) auxA += (g_probsum[j]     * invT) * (g_ohsum[j]     * invT);
            for (int j = 0; j < 4; j++) auxB += (g_probsum[4 + j] * invT) * (g_ohsum[4 + j] * invT);
            out[TT * DM] = (float)NAg * auxA + (float)NBg * auxB;
        }
    }
}

// ---------------- kernel 3: scatter tokens into expert-sorted order ----------------
__global__ void scatter_kernel() {
    int t = blockIdx.x * blockDim.x + threadIdx.x;
    if (t >= TT) return;
    int e = g_eidx[t];
    int p = atomicAdd(&g_pos[e], 1);
    g_perm[p] = t;
}

// =====================================================================
// GEMM1 (tf32 tensor cores) + fused SwiGLU
//   Block tile: M=128, 128 smem cols = 64 a-cols + 64 g-cols interleaved
//   in 8-col groups (pair p: cols [16p,16p+8)=a, [16p+8,16p+16)=g), BK=16.
//   8 warps = 2M x 4N; warp tile 64x32; 4x4 m16n8k8 mma per k8-step.
// =====================================================================
#define ASTRIDE 20
#define BSTRIDE 132

__global__ __launch_bounds__(256, 2)
void gemm1_kernel(const float* __restrict__ x,
                  const float* __restrict__ W1,
                  const float* __restrict__ b1) {
    const int e = blockIdx.z;
    const int off  = g_offsets[e];
    const int cnt  = g_offsets[e + 1] - off;
    const int row0 = blockIdx.y * 128;
    if (row0 >= cnt) return;
    const int n0b = blockIdx.x * 64;          // a-col base (g-col base = 2048 + n0b)
    const int rowsv = min(128, cnt - row0);

    __shared__ float As[2][128][ASTRIDE];
    __shared__ float Bs[2][16][BSTRIDE];
    __shared__ int   toks[128];

    const int tid = threadIdx.x;
    const int wid = tid >> 5;
    const int lane = tid & 31;
    const int g  = lane >> 2;     // groupID
    const int tg = lane & 3;      // thread-in-group
    const int wm = (wid >> 2) * 64;
    const int wn = (wid & 3) * 32;

    if (tid < 128) toks[tid] = (tid < rowsv) ? g_perm[off + row0 + tid] : -1;
    __syncthreads();

    const float* W1e = W1 + (size_t)e * DM * NH;

    // loader indices
    const int alr = tid >> 1;                 // A row
    const int alk0 = (tid & 1) * 8;           // A k chunk base (two 16B chunks)
    const int bq0 = tid;                      // B chunk ids: tid, tid+256
    // B column mapping (interleaved a/g in 8-col groups)
    auto bcolmap = [&](int c) -> int {
        int pair = c >> 4, within = c & 15;
        return (within < 8) ? (n0b + pair * 8 + within)
                            : (DFF + n0b + pair * 8 + (within - 8));
    };
    const int bcol0 = (bq0 & 31) * 4;
    const int bk0i  = bq0 >> 5;
    const int bcol1 = ((bq0 + 256) & 31) * 4;
    const int bk1i  = (bq0 + 256) >> 5;
    const int gcol0 = bcolmap(bcol0);
    const int gcol1 = bcolmap(bcol1);

    uint32_t sA0 = (uint32_t)__cvta_generic_to_shared(&As[0][alr][alk0]);
    uint32_t sA1 = (uint32_t)__cvta_generic_to_shared(&As[0][alr][alk0 + 4]);
    uint32_t sB0 = (uint32_t)__cvta_generic_to_shared(&Bs[0][bk0i][bcol0]);
    uint32_t sB1 = (uint32_t)__cvta_generic_to_shared(&Bs[0][bk1i][bcol1]);
    const uint32_t stgA = sizeof(float) * 128 * ASTRIDE;
    const uint32_t stgB = sizeof(float) * 16 * BSTRIDE;

    const int tokA = toks[alr];
    const float* srcA = (tokA >= 0) ? (x + (size_t)tokA * DM + alk0) : x;
    const int abytes = (tokA >= 0) ? 16 : 0;

    auto issue = [&](int t, int s) {
        int k0 = t * 16;
        cp16(sA0 + s * stgA, srcA + k0, abytes);
        cp16(sA1 + s * stgA, srcA + k0 + 4, abytes);
        cp16(sB0 + s * stgB, W1e + (size_t)(k0 + bk0i) * NH + gcol0, 16);
        cp16(sB1 + s * stgB, W1e + (size_t)(k0 + bk1i) * NH + gcol1, 16);
        cp_commit();
    };

    float c[4][4][4];   // [mt][nt][frag]
#pragma unroll
    for (int i = 0; i < 4; i++)
#pragma unroll
        for (int j = 0; j < 4; j++)
#pragma unroll
            for (int q = 0; q < 4; q++) c[i][j][q] = 0.f;

    const int NT = DM / 16;
    issue(0, 0);
    for (int t = 0; t < NT; t++) {
        const int s = t & 1;
        if (t + 1 < NT) { issue(t + 1, s ^ 1); cp_wait1(); }
        else            { cp_wait0(); }
        __syncthreads();

#pragma unroll
        for (int kk = 0; kk < 16; kk += 8) {
            uint32_t ra[4][4];
#pragma unroll
            for (int mt = 0; mt < 4; mt++) {
                const float* p = &As[s][wm + mt * 16 + g][kk + tg];
                ra[mt][0] = f2tf(p[0]);
                ra[mt][1] = f2tf(p[8 * ASTRIDE]);
                ra[mt][2] = f2tf(p[4]);
                ra[mt][3] = f2tf(p[8 * ASTRIDE + 4]);
            }
            uint32_t rb[4][2];
#pragma unroll
            for (int nt = 0; nt < 4; nt++) {
                const float* p = &Bs[s][kk + tg][wn + nt * 8 + g];
                rb[nt][0] = f2tf(p[0]);
                rb[nt][1] = f2tf(p[4 * BSTRIDE]);
            }
#pragma unroll
            for (int mt = 0; mt < 4; mt++)
#pragma unroll
                for (int nt = 0; nt < 4; nt++)
                    mma_tf32(c[mt][nt], ra[mt], rb[nt]);
        }
        __syncthreads();
    }

    // ---- epilogue: bias + a * silu(g) -> g_act (sorted rows) ----
    const float* b1e = b1 + (size_t)e * NH;
#pragma unroll
    for (int mt = 0; mt < 4; mt++) {
#pragma unroll
        for (int p = 0; p < 2; p++) {
            const float* ca = c[mt][2 * p];
            const float* cg = c[mt][2 * p + 1];
            int ga = n0b + ((wn >> 4) * 8) + p * 8 + 2 * tg;  // (wn/32)*16 = (wn>>4)*8
            float ba0 = b1e[ga],       ba1 = b1e[ga + 1];
            float bg0 = b1e[DFF + ga], bg1 = b1e[DFF + ga + 1];
            int r0 = wm + mt * 16 + g;
#pragma unroll
            for (int h = 0; h < 2; h++) {
                int r = r0 + h * 8;
                if (r < rowsv) {
                    float av0 = ca[2 * h] + ba0, av1 = ca[2 * h + 1] + ba1;
                    float gv0 = cg[2 * h] + bg0, gv1 = cg[2 * h + 1] + bg1;
                    float s0 = gv0 / (1.f + expf(-gv0));
                    float s1 = gv1 / (1.f + expf(-gv1));
                    float2 o = make_float2(av0 * s0, av1 * s1);
                    *(float2*)&g_act[(size_t)(off + row0 + r) * DFF + ga] = o;
                }
            }
        }
    }
}

// =====================================================================
// GEMM2 (tf32 tensor cores): act[sorted] @ W2 + b2, scatter to token order
//   Block tile M=128, N=128, BK=16. Same warp layout.
// =====================================================================
__global__ __launch_bounds__(256, 2)
void gemm2_kernel(const float* __restrict__ W2,
                  const float* __restrict__ b2,
                  float* __restrict__ out) {
    const int e = blockIdx.z;
    const int off  = g_offsets[e];
    const int cnt  = g_offsets[e + 1] - off;
    const int row0 = blockIdx.y * 128;
    if (row0 >= cnt) return;
    const int n0b = blockIdx.x * 128;
    const int rowsv = min(128, cnt - row0);

    __shared__ float As[2][128][ASTRIDE];
    __shared__ float Bs[2][16][BSTRIDE];
    __shared__ int   toks[128];

    const int tid = threadIdx.x;
    const int wid = tid >> 5;
    const int lane = tid & 31;
    const int g  = lane >> 2;
    const int tg = lane & 3;
    const int wm = (wid >> 2) * 64;
    const int wn = (wid & 3) * 32;

    if (tid < 128) toks[tid] = (tid < rowsv) ? g_perm[off + row0 + tid] : -1;
    __syncthreads();

    const float* W2e = W2 + (size_t)e * DFF * DM;

    const int alr = tid >> 1;
    const int alk0 = (tid & 1) * 8;
    const int bcol0 = (tid & 31) * 4;
    const int bk0i  = tid >> 5;
    const int bcol1 = ((tid + 256) & 31) * 4;
    const int bk1i  = (tid + 256) >> 5;

    uint32_t sA0 = (uint32_t)__cvta_generic_to_shared(&As[0][alr][alk0]);
    uint32_t sA1 = (uint32_t)__cvta_generic_to_shared(&As[0][alr][alk0 + 4]);
    uint32_t sB0 = (uint32_t)__cvta_generic_to_shared(&Bs[0][bk0i][bcol0]);
    uint32_t sB1 = (uint32_t)__cvta_generic_to_shared(&Bs[0][bk1i][bcol1]);
    const uint32_t stgA = sizeof(float) * 128 * ASTRIDE;
    const uint32_t stgB = sizeof(float) * 16 * BSTRIDE;

    const bool avalid = (alr < rowsv);
    const float* srcA = avalid ? (g_act + (size_t)(off + row0 + alr) * DFF + alk0) : g_act;
    const int abytes = avalid ? 16 : 0;

    auto issue = [&](int t, int s) {
        int k0 = t * 16;
        cp16(sA0 + s * stgA, srcA + k0, abytes);
        cp16(sA1 + s * stgA, srcA + k0 + 4, abytes);
        cp16(sB0 + s * stgB, W2e + (size_t)(k0 + bk0i) * DM + n0b + bcol0, 16);
        cp16(sB1 + s * stgB, W2e + (size_t)(k0 + bk1i) * DM + n0b + bcol1, 16);
        cp_commit();
    };

    float c[4][4][4];
#pragma unroll
    for (int i = 0; i < 4; i++)
#pragma unroll
        for (int j = 0; j < 4; j++)
#pragma unroll
            for (int q = 0; q < 4; q++) c[i][j][q] = 0.f;

    const int NT = DFF / 16;
    issue(0, 0);
    for (int t = 0; t < NT; t++) {
        const int s = t & 1;
        if (t + 1 < NT) { issue(t + 1, s ^ 1); cp_wait1(); }
        else            { cp_wait0(); }
        __syncthreads();

#pragma unroll
        for (int kk = 0; kk < 16; kk += 8) {
            uint32_t ra[4][4];
#pragma unroll
            for (int mt = 0; mt < 4; mt++) {
                const float* p = &As[s][wm + mt * 16 + g][kk + tg];
                ra[mt][0] = f2tf(p[0]);
                ra[mt][1] = f2tf(p[8 * ASTRIDE]);
                ra[mt][2] = f2tf(p[4]);
                ra[mt][3] = f2tf(p[8 * ASTRIDE + 4]);
            }
            uint32_t rb[4][2];
#pragma unroll
            for (int nt = 0; nt < 4; nt++) {
                const float* p = &Bs[s][kk + tg][wn + nt * 8 + g];
                rb[nt][0] = f2tf(p[0]);
                rb[nt][1] = f2tf(p[4 * BSTRIDE]);
            }
#pragma unroll
            for (int mt = 0; mt < 4; mt++)
#pragma unroll
                for (int nt = 0; nt < 4; nt++)
                    mma_tf32(c[mt][nt], ra[mt], rb[nt]);
        }
        __syncthreads();
    }

    // ---- epilogue: bias + scatter rows back to token order ----
    const float* b2e = b2 + (size_t)e * DM;
#pragma unroll
    for (int mt = 0; mt < 4; mt++) {
#pragma unroll
        for (int nt = 0; nt < 4; nt++) {
            int gcol = n0b + wn + nt * 8 + 2 * tg;
            float bv0 = b2e[gcol], bv1 = b2e[gcol + 1];
            int r0 = wm + mt * 16 + g;
#pragma unroll
            for (int h = 0; h < 2; h++) {
                int r = r0 + h * 8;
                if (r < rowsv) {
                    int tok = toks[r];
                    float2 o = make_float2(c[mt][nt][2 * h] + bv0,
                                           c[mt][nt][2 * h + 1] + bv1);
                    *(float2*)&out[(size_t)tok * DM + gcol] = o;
                }
            }
        }
    }
}

// ---------------- launch ----------------
extern "C" void kernel_launch(void* const* d_in, const int* in_sizes, int n_in,
                              void* d_out, int out_size) {
    const float* x   = (const float*)d_in[0];
    const float* W1  = (const float*)d_in[1];
    const float* b1  = (const float*)d_in[2];
    const float* W2  = (const float*)d_in[3];
    const float* b2  = (const float*)d_in[4];
    const float* Wga = (const float*)d_in[5];
    const float* bga = (const float*)d_in[6];
    const float* Wgb = (const float*)d_in[7];
    const float* bgb = (const float*)d_in[8];
    float* out = (float*)d_out;

    zero_kernel<<<1, 64>>>();
    gating_kernel<<<TT / 8, 256>>>(x, Wga, bga, Wgb, bgb);
    scan_kernel<<<1, 32>>>(out, out_size);
    scatter_kernel<<<TT / 256, 256>>>();
    gemm1_kernel<<<dim3(32, 16, NE), 256>>>(x, W1, b1);
    gemm2_kernel<<<dim3(8, 16, NE), 256>>>(W2, b2, out);
}